// round 3
// baseline (speedup 1.0000x reference)
#include <cuda_runtime.h>

// CASSI forward, direction-separated two-kernel pipeline.
//
//   y2[b,i,k]    = sum_l x[b,l,i,k-2l] * phi[i,k-2l]   (0 <= k-2l < N)
//   out[b,l,i,j] = phi[i,j] * y2[b,i,2l+j]
//
// K1: reads x (235MB, pure DRAM read stream), writes y2 scratch (9.3MB -> L2).
// K2: reads y2+phi (L2 hits), writes out (235MB, pure DRAM write stream).

#define B_      8
#define L_      28
#define M_      512
#define N_      512
#define STRIDE_ 2
#define NOUT_   (N_ + STRIDE_ * (L_ - 1))   // 566
#define Y2S_    568                          // row stride (16B aligned)
#define TPB     256

// L2-resident scratch: 8*512*568*4 B = 9.3 MB (zero-init at module load)
__device__ float y2_g[B_ * M_ * Y2S_];

// ─── K1: x -> y2 (pure read stream) ─────────────────────────────────────
__global__ __launch_bounds__(TPB) void cassi_k1(
    const float* __restrict__ x,
    const float* __restrict__ phi)
{
    __shared__ float phi_s[N_];

    const int bm = blockIdx.x;           // (b, i)
    const int b  = bm / M_;
    const int i  = bm % M_;
    const int t  = threadIdx.x;

    {
        const float4* p4 = reinterpret_cast<const float4*>(phi + (size_t)i * N_);
        if (t < N_ / 4)
            reinterpret_cast<float4*>(phi_s)[t] = p4[t];
    }
    __syncthreads();

    const float* xb = x + (size_t)b * (L_ * M_ * N_) + (size_t)i * N_;
    const size_t band_stride = (size_t)M_ * N_;

    // three independent scalar accumulation streams (max MLP shape from R1)
    const int k0 = t;
    const int k1 = t + TPB;
    const int k2 = t + 2 * TPB;

    float acc0 = 0.f, acc1 = 0.f, acc2 = 0.f;

    #pragma unroll
    for (int l = 0; l < L_; ++l) {
        const float* xrow = xb + (size_t)l * band_stride;
        unsigned n0 = (unsigned)(k0 - STRIDE_ * l);
        unsigned n1 = (unsigned)(k1 - STRIDE_ * l);
        unsigned n2 = (unsigned)(k2 - STRIDE_ * l);
        if (n0 < N_) acc0 += xrow[n0] * phi_s[n0];
        if (n1 < N_) acc1 += xrow[n1] * phi_s[n1];
        if (n2 < N_) acc2 += xrow[n2] * phi_s[n2];
    }

    float* yrow = y2_g + (size_t)bm * Y2S_;
    yrow[k0] = acc0;                      // k0 < 566 always
    yrow[k1] = acc1;
    if (k2 < NOUT_) yrow[k2] = acc2;      // t < 54
}

// ─── K2: y2 -> out (pure write stream) ──────────────────────────────────
__global__ __launch_bounds__(TPB) void cassi_k2(
    const float* __restrict__ phi,
    float* __restrict__ out)
{
    __shared__ float  phi_s[N_];
    __shared__ float2 y2_s[Y2S_ / 2];     // 284 float2

    const int bm = blockIdx.x;
    const int b  = bm / M_;
    const int i  = bm % M_;
    const int t  = threadIdx.x;

    {
        const float4* p4 = reinterpret_cast<const float4*>(phi + (size_t)i * N_);
        if (t < N_ / 4)
            reinterpret_cast<float4*>(phi_s)[t] = p4[t];
        const float4* y4 = reinterpret_cast<const float4*>(y2_g + (size_t)bm * Y2S_);
        if (t < Y2S_ / 4)                 // 142 float4 = 568 floats
            reinterpret_cast<float4*>(y2_s)[t] = y4[t];
    }
    __syncthreads();

    const float2 phi_reg = reinterpret_cast<const float2*>(phi_s)[t];

    float* ob = out + (size_t)b * (L_ * M_ * N_) + (size_t)i * N_ + 2 * t;
    const size_t band_stride = (size_t)M_ * N_;

    #pragma unroll
    for (int l = 0; l < L_; ++l) {
        float2 yv = y2_s[l + t];          // conflict-free LDS.64
        float2 r;
        r.x = phi_reg.x * yv.x;
        r.y = phi_reg.y * yv.y;
        *reinterpret_cast<float2*>(ob + (size_t)l * band_stride) = r;
    }
}

extern "C" void kernel_launch(void* const* d_in, const int* in_sizes, int n_in,
                              void* d_out, int out_size)
{
    const float* x   = (const float*)d_in[0];
    const float* phi = (const float*)d_in[1];
    float* out       = (float*)d_out;

    cassi_k1<<<B_ * M_, TPB>>>(x, phi);
    cassi_k2<<<B_ * M_, TPB>>>(phi, out);
}

// round 4
// speedup vs baseline: 1.1557x; 1.1557x over previous
#include <cuda_runtime.h>

// CASSI forward, fused single kernel (hybrid of R1 main loop + R2 epilogue).
//
//   y2[b,i,k]    = sum_l x[b,l,i,k-2l] * phi[i,k-2l]   (0 <= k-2l < N)
//   out[b,l,i,j] = phi[i,j] * y2[b,i,2l+j]
//
// Main loop: 3 independent scalar load streams per thread (max MLP — best
// measured DRAM%). Epilogue: thread t owns j={2t,2t+1}; y2 read is a
// conflict-free LDS.64 at float2 index (l+t). Streaming cache hints on the
// single-use x/out streams.

#define B_      8
#define L_      28
#define M_      512
#define N_      512
#define STRIDE_ 2
#define NOUT_   (N_ + STRIDE_ * (L_ - 1))   // 566
#define Y2S_    568                          // padded, 16B-aligned row
#define TPB     256

__global__ __launch_bounds__(TPB) void cassi_fused_kernel(
    const float* __restrict__ x,
    const float* __restrict__ phi,
    float* __restrict__ out)
{
    __shared__ __align__(16) float phi_s[N_];
    __shared__ __align__(16) float y2_s[Y2S_];

    const int bm = blockIdx.x;           // (b, i)
    const int b  = bm / M_;
    const int i  = bm % M_;
    const int t  = threadIdx.x;

    // ---- phi row i -> smem (float4) ----
    {
        const float4* p4 = reinterpret_cast<const float4*>(phi + (size_t)i * N_);
        if (t < N_ / 4)
            reinterpret_cast<float4*>(phi_s)[t] = p4[t];
    }
    __syncthreads();

    const float* xb = x + (size_t)b * (L_ * M_ * N_) + (size_t)i * N_;
    const size_t band_stride = (size_t)M_ * N_;

    // ---- main loop: 3 independent scalar accumulation streams ----
    const int k0 = t;
    const int k1 = t + TPB;
    const int k2 = t + 2 * TPB;

    float acc0 = 0.f, acc1 = 0.f, acc2 = 0.f;

    #pragma unroll
    for (int l = 0; l < L_; ++l) {
        const float* xrow = xb + (size_t)l * band_stride;
        unsigned n0 = (unsigned)(k0 - STRIDE_ * l);
        unsigned n1 = (unsigned)(k1 - STRIDE_ * l);
        unsigned n2 = (unsigned)(k2 - STRIDE_ * l);
        if (n0 < N_) acc0 += __ldcs(xrow + n0) * phi_s[n0];
        if (n1 < N_) acc1 += __ldcs(xrow + n1) * phi_s[n1];
        if (n2 < N_) acc2 += __ldcs(xrow + n2) * phi_s[n2];
    }

    y2_s[k0] = acc0;                      // stride-1: conflict-free
    y2_s[k1] = acc1;
    if (k2 < NOUT_) y2_s[k2] = acc2;      // t < 54
    __syncthreads();

    // ---- epilogue: thread t -> output columns j = {2t, 2t+1} ----
    // y2 word offset 2l+2t == float2 index (l+t): conflict-free LDS.64.
    const float2 phi_reg = reinterpret_cast<const float2*>(phi_s)[t];
    float* ob = out + (size_t)b * (L_ * M_ * N_) + (size_t)i * N_ + 2 * t;

    #pragma unroll
    for (int l = 0; l < L_; ++l) {
        float2 yv = reinterpret_cast<const float2*>(y2_s)[l + t];
        float2 r;
        r.x = phi_reg.x * yv.x;
        r.y = phi_reg.y * yv.y;
        __stcs(reinterpret_cast<float2*>(ob + (size_t)l * band_stride), r);
    }
}

extern "C" void kernel_launch(void* const* d_in, const int* in_sizes, int n_in,
                              void* d_out, int out_size)
{
    const float* x   = (const float*)d_in[0];
    const float* phi = (const float*)d_in[1];
    float* out       = (float*)d_out;

    cassi_fused_kernel<<<B_ * M_, TPB>>>(x, phi, out);
}